// round 16
// baseline (speedup 1.0000x reference)
#include <cuda_runtime.h>
#include <cuda_fp16.h>
#include <math.h>
#include <stdint.h>

// Problem constants
#define B_   16
#define T_   243
#define J_   24
#define D_   256
#define H_   8
#define DH_  32
#define BJ_  (B_ * J_)          // 384
#define M_   (BJ_ * T_)         // 93312
#define N_   (3 * D_)           // 768
#define K_   D_                 // 256

// fp16 copies of inputs (X permuted to m-major: row m = (b*J+j)*T + t)
__device__ __half g_xh[(size_t)M_ * K_];
__device__ __half g_wh[(size_t)N_ * K_];
// Scratch: q/k/v fp16, [bj*H + h][t][dh] layout
__device__ __half g_q[BJ_ * H_ * T_ * DH_];
__device__ __half g_k[BJ_ * H_ * T_ * DH_];
__device__ __half g_v[BJ_ * H_ * T_ * DH_];

// ---------------------------------------------------------------------------
// helpers
// ---------------------------------------------------------------------------
__device__ __forceinline__ uint32_t smem_u32(const void* p) {
    uint32_t a;
    asm("{ .reg .u64 t; cvta.to.shared.u64 t, %1; cvt.u32.u64 %0, t; }" : "=r"(a) : "l"(p));
    return a;
}
__device__ __forceinline__ void ldsm_x4(uint32_t r[4], uint32_t addr) {
    asm volatile("ldmatrix.sync.aligned.m8n8.x4.shared.b16 {%0,%1,%2,%3}, [%4];"
                 : "=r"(r[0]), "=r"(r[1]), "=r"(r[2]), "=r"(r[3]) : "r"(addr));
}
__device__ __forceinline__ void mma_f16(float c[4], const uint32_t a[4],
                                        uint32_t b0, uint32_t b1) {
    asm volatile(
        "mma.sync.aligned.m16n8k16.row.col.f32.f16.f16.f32 "
        "{%0,%1,%2,%3}, {%4,%5,%6,%7}, {%8,%9}, {%0,%1,%2,%3};\n"
        : "+f"(c[0]), "+f"(c[1]), "+f"(c[2]), "+f"(c[3])
        : "r"(a[0]), "r"(a[1]), "r"(a[2]), "r"(a[3]), "r"(b0), "r"(b1));
}
__device__ __forceinline__ void mma_f16acc(uint32_t c[2], const uint32_t a[4],
                                           uint32_t b0, uint32_t b1) {
    asm volatile(
        "mma.sync.aligned.m16n8k16.row.col.f16.f16.f16.f16 "
        "{%0,%1}, {%2,%3,%4,%5}, {%6,%7}, {%0,%1};\n"
        : "+r"(c[0]), "+r"(c[1])
        : "r"(a[0]), "r"(a[1]), "r"(a[2]), "r"(a[3]), "r"(b0), "r"(b1));
}
__device__ __forceinline__ uint4 pack8h(float4 a, float4 b) {
    uint4 u;
    __half2 h;
    h = __floats2half2_rn(a.x, a.y); u.x = *(uint32_t*)&h;
    h = __floats2half2_rn(a.z, a.w); u.y = *(uint32_t*)&h;
    h = __floats2half2_rn(b.x, b.y); u.z = *(uint32_t*)&h;
    h = __floats2half2_rn(b.z, b.w); u.w = *(uint32_t*)&h;
    return u;
}
__device__ __forceinline__ float2 h2f(uint32_t u) {
    __half2 h = *reinterpret_cast<__half2*>(&u);
    return __half22float2(h);
}
__device__ __forceinline__ __half2 u2h2(uint32_t u) {
    return *reinterpret_cast<__half2*>(&u);
}

#define CP_ASYNC16(dst, src) \
    asm volatile("cp.async.cg.shared.global [%0], [%1], 16;" :: "r"(dst), "l"(src) : "memory")
#define CP_COMMIT() asm volatile("cp.async.commit_group;" ::: "memory")
#define CP_WAIT(n)  asm volatile("cp.async.wait_group %0;" :: "n"(n) : "memory")

// ---------------------------------------------------------------------------
// Kernel 0: convert X (permute to m-major) and W to fp16.
// ---------------------------------------------------------------------------
#define XROWS_CTA 8
#define CONV_GRID (M_ / XROWS_CTA + N_ / XROWS_CTA)

__global__ void __launch_bounds__(256)
convert_kernel(const float* __restrict__ X, const float* __restrict__ Wq)
{
    const int lane = threadIdx.x & 31;
    const int wrp  = threadIdx.x >> 5;
    const int off  = lane * 8;

    if (blockIdx.x < M_ / XROWS_CTA) {
        int r = blockIdx.x * XROWS_CTA + wrp;
        int b   = r / (T_ * J_);
        int rem = r - b * (T_ * J_);
        int t   = rem / J_;
        int j   = rem - t * J_;
        int m   = (b * J_ + j) * T_ + t;
        const float* src = X + (size_t)r * D_ + off;
        float4 a0 = *(const float4*)(src);
        float4 a1 = *(const float4*)(src + 4);
        *(uint4*)&g_xh[(size_t)m * K_ + off] = pack8h(a0, a1);
    } else {
        int n = (blockIdx.x - M_ / XROWS_CTA) * XROWS_CTA + wrp;
        const float* src = Wq + (size_t)n * K_ + off;
        float4 a0 = *(const float4*)(src);
        float4 a1 = *(const float4*)(src + 4);
        *(uint4*)&g_wh[(size_t)n * K_ + off] = pack8h(a0, a1);
    }
}

// ---------------------------------------------------------------------------
// QKV GEMM, templated on accumulator precision.
//   F16A=true : q/k n-blocks (error only enters softmax logits -- benign)
//   F16A=false: v n-blocks (f32 acc, output-critical precision preserved)
// Structure identical to R13/R15 (3-stage cp.async, SW128, ldmatrix, 2 CTA/SM).
// ---------------------------------------------------------------------------
#define BM 128
#define BN 128
#define NSTAGE 3
#define STAGE_SZ 32768
#define CSTR2 132
#define GOFF_BIAS (NSTAGE * STAGE_SZ)
#define GEMM_SMEM (GOFF_BIAS + 512)

template<bool F16A>
__global__ void __launch_bounds__(256, 2)
qkv_gemm_t(const float* __restrict__ bias, int nblk_off)
{
    extern __shared__ char smem[];
    const uint32_t sb = smem_u32(smem);
    float* sBias = (float*)(smem + GOFF_BIAS);

    const int tid  = threadIdx.x;
    const int lane = tid & 31;
    const int warp = tid >> 5;
    const int wm   = warp & 3;
    const int wn   = warp >> 2;
    const int m_base = blockIdx.y * BM;
    const int n_base = (blockIdx.x + nblk_off) * BN;

    if (tid < 128) sBias[tid] = bias[n_base + tid];

    const int lrow = tid >> 3;
    const int lk   = (tid & 7) * 8;
    const __half* aR[4];
    const __half* bR[4];
    uint32_t so[4];
    #pragma unroll
    for (int jj = 0; jj < 4; ++jj) {
        int row = lrow + jj * 32;
        aR[jj] = g_xh + (size_t)(m_base + row) * K_ + lk;
        bR[jj] = g_wh + (size_t)(n_base + row) * K_ + lk;
        so[jj] = row * 128 + 16 * ((tid & 7) ^ (row & 7));
    }

    const int jrow = lane & 7;
    const int nlo  = (lane >> 3) & 1;
    const int hi   = lane >> 4;
    uint32_t abase[2], ar7[2];
    #pragma unroll
    for (int mi = 0; mi < 2; ++mi) {
        int r = wm * 32 + mi * 16 + nlo * 8 + jrow;
        abase[mi] = r * 128;
        ar7[mi] = r & 7;
    }
    uint32_t bbase[4], br7[4];
    #pragma unroll
    for (int p = 0; p < 4; ++p) {
        int r = wn * 64 + p * 16 + nlo * 8 + jrow;
        bbase[p] = 16384 + r * 128;
        br7[p] = r & 7;
    }

    float    accf[F16A ? 1 : 2][8][4];
    uint32_t acch[F16A ? 2 : 1][8][2];
    if (F16A) {
        #pragma unroll
        for (int mi = 0; mi < 2; ++mi)
            #pragma unroll
            for (int ni = 0; ni < 8; ++ni) {
                acch[mi][ni][0] = 0u;
                acch[mi][ni][1] = 0u;
            }
    } else {
        #pragma unroll
        for (int mi = 0; mi < 2; ++mi)
            #pragma unroll
            for (int ni = 0; ni < 8; ++ni)
                #pragma unroll
                for (int r = 0; r < 4; ++r)
                    accf[mi][ni][r] = 0.0f;
    }

#define ISSUE_STAGE(s, kb) do {                                        \
        uint32_t _b = sb + (s) * STAGE_SZ;                             \
        const int _o = (kb) * 64;                                      \
        CP_ASYNC16(_b + so[0],         (const char*)(aR[0] + _o));     \
        CP_ASYNC16(_b + so[1],         (const char*)(aR[1] + _o));     \
        CP_ASYNC16(_b + so[2],         (const char*)(aR[2] + _o));     \
        CP_ASYNC16(_b + so[3],         (const char*)(aR[3] + _o));     \
        CP_ASYNC16(_b + 16384 + so[0], (const char*)(bR[0] + _o));     \
        CP_ASYNC16(_b + 16384 + so[1], (const char*)(bR[1] + _o));     \
        CP_ASYNC16(_b + 16384 + so[2], (const char*)(bR[2] + _o));     \
        CP_ASYNC16(_b + 16384 + so[3], (const char*)(bR[3] + _o));     \
    } while (0)

    ISSUE_STAGE(0, 0); CP_COMMIT();
    ISSUE_STAGE(1, 1); CP_COMMIT();

    #pragma unroll 1
    for (int kb = 0; kb < 4; ++kb) {
        if (kb == 3) { CP_WAIT(0); } else { CP_WAIT(1); }
        __syncthreads();

        if (kb < 2) { ISSUE_STAGE((kb + 2) % NSTAGE, kb + 2); CP_COMMIT(); }

        const uint32_t stg = sb + (kb % NSTAGE) * STAGE_SZ;
        #pragma unroll
        for (int ks = 0; ks < 4; ++ks) {
            const uint32_t cp = 2 * ks + hi;
            uint32_t bfr[4][4];
            #pragma unroll
            for (int p = 0; p < 4; ++p)
                ldsm_x4(bfr[p], stg + bbase[p] + ((cp ^ br7[p]) << 4));
            #pragma unroll
            for (int mi = 0; mi < 2; ++mi) {
                uint32_t afr[4];
                ldsm_x4(afr, stg + abase[mi] + ((cp ^ ar7[mi]) << 4));
                #pragma unroll
                for (int p = 0; p < 4; ++p) {
                    if (F16A) {
                        mma_f16acc(acch[mi][2 * p + 0], afr, bfr[p][0], bfr[p][2]);
                        mma_f16acc(acch[mi][2 * p + 1], afr, bfr[p][1], bfr[p][3]);
                    } else {
                        mma_f16(accf[mi][2 * p + 0], afr, bfr[p][0], bfr[p][2]);
                        mma_f16(accf[mi][2 * p + 1], afr, bfr[p][1], bfr[p][3]);
                    }
                }
            }
        }
    }
    __syncthreads();
#undef ISSUE_STAGE

    float* Cs = (float*)smem;
    const int gi = lane >> 2;
    const int tg = lane & 3;
    #pragma unroll
    for (int ni = 0; ni < 8; ++ni) {
        int nn = wn * 64 + ni * 8 + 2 * tg;
        float b0 = sBias[nn];
        float b1 = sBias[nn + 1];
        #pragma unroll
        for (int mi = 0; mi < 2; ++mi) {
            #pragma unroll
            for (int rr = 0; rr < 2; ++rr) {
                int mm = wm * 32 + mi * 16 + rr * 8 + gi;
                float2 v;
                if (F16A) {
                    float2 f = h2f(acch[mi][ni][rr]);
                    v.x = f.x + b0;
                    v.y = f.y + b1;
                } else {
                    v.x = accf[mi][ni][rr * 2 + 0] + b0;
                    v.y = accf[mi][ni][rr * 2 + 1] + b1;
                }
                *(float2*)&Cs[mm * CSTR2 + nn] = v;
            }
        }
    }
    __syncthreads();

    const int sel = n_base >> 8;
    __half* dst = (sel == 0) ? g_q : (sel == 1) ? g_k : g_v;
    #pragma unroll 1
    for (int pass = 0; pass < 16; ++pass) {
        int mm  = pass * 8 + (tid >> 5);
        int nn4 = (tid & 31) * 4;
        int m   = m_base + mm;
        int bj  = m / T_;
        int t   = m - bj * T_;
        int n   = n_base + nn4;
        int h   = (n >> 5) & 7;
        int dd  = n & 31;
        size_t idx = (size_t)((bj * H_ + h) * T_ + t) * DH_ + dd;
        float4 val = *(const float4*)&Cs[mm * CSTR2 + nn4];
        __half2 p0 = __floats2half2_rn(val.x, val.y);
        __half2 p1 = __floats2half2_rn(val.z, val.w);
        uint2 u;
        u.x = *(uint32_t*)&p0;
        u.y = *(uint32_t*)&p1;
        *(uint2*)&dst[idx] = u;
    }
}

// ---------------------------------------------------------------------------
// Windowed attention v5b. One CTA per (bj, h).
// K and V staged via cp.async in SEPARATE commit groups: logits start as
// soon as K lands (V still in flight, drained before the V loop).
// ---------------------------------------------------------------------------
#define KSTR 40   // halves
#define VSTR 40   // halves
#define OSTR 36   // floats
#define AOFF_V 34992
#define ATT_SMEM (AOFF_V + T_ * VSTR * 2)  // 54432 -> 4 CTAs/SM

__global__ void __launch_bounds__(256, 4)
attn_kernel(const float* __restrict__ tau, float* __restrict__ out)
{
    extern __shared__ char sma[];
    const uint32_t sb = smem_u32(sma);
    __half* Ks = (__half*)sma;
    __half* Vs = (__half*)(sma + AOFF_V);
    float*  Os = (float*)sma;

    const int bjh = blockIdx.x;
    const int bj  = bjh >> 3;
    const int h   = bjh & 7;
    const int b   = bj / J_;
    const int j   = bj - b * J_;
    const size_t base = (size_t)bjh * (T_ * DH_);

    const int t  = threadIdx.x;
    const bool tv = (t < T_);
    const int  tc = tv ? t : (T_ - 1);

    // Stage K (group 1), then V (group 0) via cp.async
    {
        const char* kg = (const char*)(g_k + base);
        const char* vg = (const char*)(g_v + base);
        for (int i8 = threadIdx.x; i8 < T_ * DH_ / 8; i8 += 256) {
            int tt = i8 >> 2;
            int d8 = (i8 & 3) << 3;
            CP_ASYNC16(sb + (tt * KSTR + d8) * 2, kg + i8 * 16);
        }
        CP_COMMIT();
        for (int i8 = threadIdx.x; i8 < T_ * DH_ / 8; i8 += 256) {
            int tt = i8 >> 2;
            int d8 = (i8 & 3) << 3;
            CP_ASYNC16(sb + AOFF_V + (tt * VSTR + d8) * 2, vg + i8 * 16);
        }
        CP_COMMIT();
    }

    // Q -> 16 half2 registers (overlaps staging)
    uint32_t qh[16];
    {
        const uint4* qrow = (const uint4*)(g_q + base + (size_t)tc * DH_);
        #pragma unroll
        for (int i = 0; i < 4; ++i) {
            uint4 u = qrow[i];
            qh[i * 4 + 0] = u.x; qh[i * 4 + 1] = u.y;
            qh[i * 4 + 2] = u.z; qh[i * 4 + 3] = u.w;
        }
    }

    const float scale = 1.0f / (sqrtf(32.0f) * fmaxf(tau[h], 1e-3f));

    int  tox[9];
    bool ov[9];
    #pragma unroll
    for (int o = 0; o < 9; ++o) {
        int to = tc + o - 4;
        ov[o]  = (to >= 0) && (to < T_);
        tox[o] = min(max(to, 0), T_ - 1);
    }

    CP_WAIT(1);        // K landed (V may still be in flight)
    __syncthreads();

    // ---- logits: LDS.128 fp16 K + packed hfma2 ----
    __half2 lac[9];
    #pragma unroll
    for (int o = 0; o < 9; ++o) lac[o] = __float2half2_rn(0.0f);

    #pragma unroll
    for (int d8 = 0; d8 < 4; ++d8) {
        const __half2 q0 = u2h2(qh[d8 * 4 + 0]);
        const __half2 q1 = u2h2(qh[d8 * 4 + 1]);
        const __half2 q2 = u2h2(qh[d8 * 4 + 2]);
        const __half2 q3 = u2h2(qh[d8 * 4 + 3]);
        #pragma unroll
        for (int o = 0; o < 9; ++o) {
            uint4 ku = *(const uint4*)&Ks[tox[o] * KSTR + d8 * 8];
            lac[o] = __hfma2(u2h2(ku.x), q0, lac[o]);
            lac[o] = __hfma2(u2h2(ku.y), q1, lac[o]);
            lac[o] = __hfma2(u2h2(ku.z), q2, lac[o]);
            lac[o] = __hfma2(u2h2(ku.w), q3, lac[o]);
        }
    }

    float logit[9];
    float mx = -1e30f;
    #pragma unroll
    for (int o = 0; o < 9; ++o) {
        float2 f = __half22float2(lac[o]);
        logit[o] = ov[o] ? (f.x + f.y) * scale : -1e30f;
        mx = fmaxf(mx, logit[o]);
    }
    float w[9];
    float s = 0.0f;
    #pragma unroll
    for (int o = 0; o < 9; ++o) {
        w[o] = ov[o] ? __expf(logit[o] - mx) : 0.0f;
        s += w[o];
    }
    const float inv = 1.0f / s;
    #pragma unroll
    for (int o = 0; o < 9; ++o) w[o] *= inv;

    CP_WAIT(0);        // V landed
    __syncthreads();   // also: all K reads done before Os overlay

    // ---- V aggregation: uint4 LDS.128 + cvt + f32 FFMA ----
    #pragma unroll
    for (int d8 = 0; d8 < 4; ++d8) {
        float a[8];
        #pragma unroll
        for (int i = 0; i < 8; ++i) a[i] = 0.0f;
        #pragma unroll
        for (int o = 0; o < 9; ++o) {
            uint4 vu = *(const uint4*)&Vs[tox[o] * VSTR + d8 * 8];
            float2 v0 = h2f(vu.x), v1 = h2f(vu.y);
            float2 v2 = h2f(vu.z), v3 = h2f(vu.w);
            a[0] += w[o] * v0.x; a[1] += w[o] * v0.y;
            a[2] += w[o] * v1.x; a[3] += w[o] * v1.y;
            a[4] += w[o] * v2.x; a[5] += w[o] * v2.y;
            a[6] += w[o] * v3.x; a[7] += w[o] * v3.y;
        }
        if (tv) {
            *(float4*)&Os[tc * OSTR + d8 * 8]     = make_float4(a[0], a[1], a[2], a[3]);
            *(float4*)&Os[tc * OSTR + d8 * 8 + 4] = make_float4(a[4], a[5], a[6], a[7]);
        }
    }
    __syncthreads();

    // Coalesced output: out[b, t, j, h*32 + d]
    for (int i4 = threadIdx.x; i4 < T_ * DH_ / 4; i4 += 256) {
        int tt = i4 >> 3;
        int d4 = (i4 & 7) << 2;
        float4 a = *(const float4*)&Os[tt * OSTR + d4];
        float* orow = out + ((size_t)((b * T_ + tt) * J_ + j) * D_) + h * DH_;
        *(float4*)(orow + d4) = a;
    }
}

// ---------------------------------------------------------------------------
extern "C" void kernel_launch(void* const* d_in, const int* in_sizes, int n_in,
                              void* d_out, int out_size)
{
    (void)in_sizes; (void)n_in; (void)out_size;
    const float* x    = (const float*)d_in[0];
    const float* Wq   = (const float*)d_in[1];
    const float* bias = (const float*)d_in[2];
    const float* tau  = (const float*)d_in[3];
    float* out = (float*)d_out;

    cudaFuncSetAttribute(qkv_gemm_t<true>,
                         cudaFuncAttributeMaxDynamicSharedMemorySize, GEMM_SMEM);
    cudaFuncSetAttribute(qkv_gemm_t<false>,
                         cudaFuncAttributeMaxDynamicSharedMemorySize, GEMM_SMEM);
    cudaFuncSetAttribute(attn_kernel,
                         cudaFuncAttributeMaxDynamicSharedMemorySize, ATT_SMEM);

    convert_kernel<<<CONV_GRID, 256>>>(x, Wq);
    // q/k blocks (n 0..511): f16 accumulate (softmax-path only)
    qkv_gemm_t<true><<<dim3(4, M_ / BM), 256, GEMM_SMEM>>>(bias, 0);
    // v blocks (n 512..767): f32 accumulate (output-critical)
    qkv_gemm_t<false><<<dim3(2, M_ / BM), 256, GEMM_SMEM>>>(bias, 4);
    attn_kernel<<<BJ_ * H_, 256, ATT_SMEM>>>(tau, out);
}

// round 17
// speedup vs baseline: 1.0430x; 1.0430x over previous
#include <cuda_runtime.h>
#include <cuda_fp16.h>
#include <math.h>
#include <stdint.h>

// Problem constants
#define B_   16
#define T_   243
#define J_   24
#define D_   256
#define H_   8
#define DH_  32
#define BJ_  (B_ * J_)          // 384
#define M_   (BJ_ * T_)         // 93312
#define N_   (3 * D_)           // 768
#define K_   D_                 // 256

// fp16 copies of inputs (X permuted to m-major: row m = (b*J+j)*T + t)
__device__ __half g_xh[(size_t)M_ * K_];
__device__ __half g_wh[(size_t)N_ * K_];
// Scratch: q/k/v fp16, [bj*H + h][t][dh] layout
__device__ __half g_q[BJ_ * H_ * T_ * DH_];
__device__ __half g_k[BJ_ * H_ * T_ * DH_];
__device__ __half g_v[BJ_ * H_ * T_ * DH_];

// ---------------------------------------------------------------------------
// helpers
// ---------------------------------------------------------------------------
__device__ __forceinline__ uint32_t smem_u32(const void* p) {
    uint32_t a;
    asm("{ .reg .u64 t; cvta.to.shared.u64 t, %1; cvt.u32.u64 %0, t; }" : "=r"(a) : "l"(p));
    return a;
}
__device__ __forceinline__ void ldsm_x4(uint32_t r[4], uint32_t addr) {
    asm volatile("ldmatrix.sync.aligned.m8n8.x4.shared.b16 {%0,%1,%2,%3}, [%4];"
                 : "=r"(r[0]), "=r"(r[1]), "=r"(r[2]), "=r"(r[3]) : "r"(addr));
}
__device__ __forceinline__ void mma_f16(float c[4], const uint32_t a[4],
                                        uint32_t b0, uint32_t b1) {
    asm volatile(
        "mma.sync.aligned.m16n8k16.row.col.f32.f16.f16.f32 "
        "{%0,%1,%2,%3}, {%4,%5,%6,%7}, {%8,%9}, {%0,%1,%2,%3};\n"
        : "+f"(c[0]), "+f"(c[1]), "+f"(c[2]), "+f"(c[3])
        : "r"(a[0]), "r"(a[1]), "r"(a[2]), "r"(a[3]), "r"(b0), "r"(b1));
}
__device__ __forceinline__ void mma_f16acc(uint32_t c[2], const uint32_t a[4],
                                           uint32_t b0, uint32_t b1) {
    asm volatile(
        "mma.sync.aligned.m16n8k16.row.col.f16.f16.f16.f16 "
        "{%0,%1}, {%2,%3,%4,%5}, {%6,%7}, {%0,%1};\n"
        : "+r"(c[0]), "+r"(c[1])
        : "r"(a[0]), "r"(a[1]), "r"(a[2]), "r"(a[3]), "r"(b0), "r"(b1));
}
__device__ __forceinline__ uint4 pack8h(float4 a, float4 b) {
    uint4 u;
    __half2 h;
    h = __floats2half2_rn(a.x, a.y); u.x = *(uint32_t*)&h;
    h = __floats2half2_rn(a.z, a.w); u.y = *(uint32_t*)&h;
    h = __floats2half2_rn(b.x, b.y); u.z = *(uint32_t*)&h;
    h = __floats2half2_rn(b.z, b.w); u.w = *(uint32_t*)&h;
    return u;
}
__device__ __forceinline__ float2 h2f(uint32_t u) {
    __half2 h = *reinterpret_cast<__half2*>(&u);
    return __half22float2(h);
}
__device__ __forceinline__ __half2 u2h2(uint32_t u) {
    return *reinterpret_cast<__half2*>(&u);
}

#define CP_ASYNC16(dst, src) \
    asm volatile("cp.async.cg.shared.global [%0], [%1], 16;" :: "r"(dst), "l"(src) : "memory")
#define CP_COMMIT() asm volatile("cp.async.commit_group;" ::: "memory")
#define CP_WAIT(n)  asm volatile("cp.async.wait_group %0;" :: "n"(n) : "memory")

// ---------------------------------------------------------------------------
// Kernel 0: convert X (permute to m-major) and W to fp16.
// ---------------------------------------------------------------------------
#define XROWS_CTA 8
#define CONV_GRID (M_ / XROWS_CTA + N_ / XROWS_CTA)

__global__ void __launch_bounds__(256)
convert_kernel(const float* __restrict__ X, const float* __restrict__ Wq)
{
    const int lane = threadIdx.x & 31;
    const int wrp  = threadIdx.x >> 5;
    const int off  = lane * 8;

    if (blockIdx.x < M_ / XROWS_CTA) {
        int r = blockIdx.x * XROWS_CTA + wrp;
        int b   = r / (T_ * J_);
        int rem = r - b * (T_ * J_);
        int t   = rem / J_;
        int j   = rem - t * J_;
        int m   = (b * J_ + j) * T_ + t;
        const float* src = X + (size_t)r * D_ + off;
        float4 a0 = *(const float4*)(src);
        float4 a1 = *(const float4*)(src + 4);
        *(uint4*)&g_xh[(size_t)m * K_ + off] = pack8h(a0, a1);
    } else {
        int n = (blockIdx.x - M_ / XROWS_CTA) * XROWS_CTA + wrp;
        const float* src = Wq + (size_t)n * K_ + off;
        float4 a0 = *(const float4*)(src);
        float4 a1 = *(const float4*)(src + 4);
        *(uint4*)&g_wh[(size_t)n * K_ + off] = pack8h(a0, a1);
    }
}

// ---------------------------------------------------------------------------
// QKV GEMM: single launch, accumulate mode per n-block (uniform branch):
//   q/k blocks (sel<2): f16 accumulate (error enters only via softmax logits)
//   v block   (sel==2): f32 accumulate (output-critical)
// Structure: 3-stage cp.async, SW128, ldmatrix, 2 CTAs/SM (R13-proven).
// ---------------------------------------------------------------------------
#define BM 128
#define BN 128
#define NSTAGE 3
#define STAGE_SZ 32768
#define CSTR2 132
#define GOFF_BIAS (NSTAGE * STAGE_SZ)
#define GEMM_SMEM (GOFF_BIAS + 512)

#define ISSUE_STAGE(s, kb) do {                                        \
        uint32_t _b = sb + (s) * STAGE_SZ;                             \
        const int _o = (kb) * 64;                                      \
        CP_ASYNC16(_b + so[0],         (const char*)(aR[0] + _o));     \
        CP_ASYNC16(_b + so[1],         (const char*)(aR[1] + _o));     \
        CP_ASYNC16(_b + so[2],         (const char*)(aR[2] + _o));     \
        CP_ASYNC16(_b + so[3],         (const char*)(aR[3] + _o));     \
        CP_ASYNC16(_b + 16384 + so[0], (const char*)(bR[0] + _o));     \
        CP_ASYNC16(_b + 16384 + so[1], (const char*)(bR[1] + _o));     \
        CP_ASYNC16(_b + 16384 + so[2], (const char*)(bR[2] + _o));     \
        CP_ASYNC16(_b + 16384 + so[3], (const char*)(bR[3] + _o));     \
    } while (0)

// Mainloop + accumulator writeback into Cs (smem bounce). Inlined twice
// under a uniform per-block branch; only one path executes per CTA.
template<bool F16A>
__device__ __forceinline__ void gemm_body(
    uint32_t sb, const __half* const aR[4], const __half* const bR[4],
    const uint32_t so[4], const uint32_t abase[2], const uint32_t ar7[2],
    const uint32_t bbase[4], const uint32_t br7[4], int hi,
    float* Cs, const float* sBias, int wm, int wn, int gi, int tg)
{
    float    accf[F16A ? 1 : 2][8][4];
    uint32_t acch[F16A ? 2 : 1][8][2];
    if (F16A) {
        #pragma unroll
        for (int mi = 0; mi < 2; ++mi)
            #pragma unroll
            for (int ni = 0; ni < 8; ++ni) {
                acch[mi][ni][0] = 0u;
                acch[mi][ni][1] = 0u;
            }
    } else {
        #pragma unroll
        for (int mi = 0; mi < 2; ++mi)
            #pragma unroll
            for (int ni = 0; ni < 8; ++ni)
                #pragma unroll
                for (int r = 0; r < 4; ++r)
                    accf[mi][ni][r] = 0.0f;
    }

    ISSUE_STAGE(0, 0); CP_COMMIT();
    ISSUE_STAGE(1, 1); CP_COMMIT();

    #pragma unroll 1
    for (int kb = 0; kb < 4; ++kb) {
        if (kb == 3) { CP_WAIT(0); } else { CP_WAIT(1); }
        __syncthreads();

        if (kb < 2) { ISSUE_STAGE((kb + 2) % NSTAGE, kb + 2); CP_COMMIT(); }

        const uint32_t stg = sb + (kb % NSTAGE) * STAGE_SZ;
        #pragma unroll
        for (int ks = 0; ks < 4; ++ks) {
            const uint32_t cp = 2 * ks + hi;
            uint32_t bfr[4][4];
            #pragma unroll
            for (int p = 0; p < 4; ++p)
                ldsm_x4(bfr[p], stg + bbase[p] + ((cp ^ br7[p]) << 4));
            #pragma unroll
            for (int mi = 0; mi < 2; ++mi) {
                uint32_t afr[4];
                ldsm_x4(afr, stg + abase[mi] + ((cp ^ ar7[mi]) << 4));
                #pragma unroll
                for (int p = 0; p < 4; ++p) {
                    if (F16A) {
                        mma_f16acc(acch[mi][2 * p + 0], afr, bfr[p][0], bfr[p][2]);
                        mma_f16acc(acch[mi][2 * p + 1], afr, bfr[p][1], bfr[p][3]);
                    } else {
                        mma_f16(accf[mi][2 * p + 0], afr, bfr[p][0], bfr[p][2]);
                        mma_f16(accf[mi][2 * p + 1], afr, bfr[p][1], bfr[p][3]);
                    }
                }
            }
        }
    }
    __syncthreads();

    #pragma unroll
    for (int ni = 0; ni < 8; ++ni) {
        int nn = wn * 64 + ni * 8 + 2 * tg;
        float b0 = sBias[nn];
        float b1 = sBias[nn + 1];
        #pragma unroll
        for (int mi = 0; mi < 2; ++mi) {
            #pragma unroll
            for (int rr = 0; rr < 2; ++rr) {
                int mm = wm * 32 + mi * 16 + rr * 8 + gi;
                float2 v;
                if (F16A) {
                    float2 f = h2f(acch[mi][ni][rr]);
                    v.x = f.x + b0;
                    v.y = f.y + b1;
                } else {
                    v.x = accf[mi][ni][rr * 2 + 0] + b0;
                    v.y = accf[mi][ni][rr * 2 + 1] + b1;
                }
                *(float2*)&Cs[mm * CSTR2 + nn] = v;
            }
        }
    }
}

__global__ void __launch_bounds__(256, 2)
qkv_gemm(const float* __restrict__ bias)
{
    extern __shared__ char smem[];
    const uint32_t sb = smem_u32(smem);
    float* sBias = (float*)(smem + GOFF_BIAS);

    const int tid  = threadIdx.x;
    const int lane = tid & 31;
    const int warp = tid >> 5;
    const int wm   = warp & 3;
    const int wn   = warp >> 2;
    const int m_base = blockIdx.y * BM;
    const int n_base = blockIdx.x * BN;

    if (tid < 128) sBias[tid] = bias[n_base + tid];

    const int lrow = tid >> 3;
    const int lk   = (tid & 7) * 8;
    const __half* aR[4];
    const __half* bR[4];
    uint32_t so[4];
    #pragma unroll
    for (int jj = 0; jj < 4; ++jj) {
        int row = lrow + jj * 32;
        aR[jj] = g_xh + (size_t)(m_base + row) * K_ + lk;
        bR[jj] = g_wh + (size_t)(n_base + row) * K_ + lk;
        so[jj] = row * 128 + 16 * ((tid & 7) ^ (row & 7));
    }

    const int jrow = lane & 7;
    const int nlo  = (lane >> 3) & 1;
    const int hi   = lane >> 4;
    uint32_t abase[2], ar7[2];
    #pragma unroll
    for (int mi = 0; mi < 2; ++mi) {
        int r = wm * 32 + mi * 16 + nlo * 8 + jrow;
        abase[mi] = r * 128;
        ar7[mi] = r & 7;
    }
    uint32_t bbase[4], br7[4];
    #pragma unroll
    for (int p = 0; p < 4; ++p) {
        int r = wn * 64 + p * 16 + nlo * 8 + jrow;
        bbase[p] = 16384 + r * 128;
        br7[p] = r & 7;
    }

    float* Cs = (float*)smem;
    const int gi = lane >> 2;
    const int tg = lane & 3;
    const int sel = n_base >> 8;   // 0=q, 1=k, 2=v (uniform per block)

    if (sel < 2) {
        gemm_body<true >(sb, aR, bR, so, abase, ar7, bbase, br7, hi,
                         Cs, sBias, wm, wn, gi, tg);
    } else {
        gemm_body<false>(sb, aR, bR, so, abase, ar7, bbase, br7, hi,
                         Cs, sBias, wm, wn, gi, tg);
    }
    __syncthreads();

    __half* dst = (sel == 0) ? g_q : (sel == 1) ? g_k : g_v;
    #pragma unroll 1
    for (int pass = 0; pass < 16; ++pass) {
        int mm  = pass * 8 + (tid >> 5);
        int nn4 = (tid & 31) * 4;
        int m   = m_base + mm;
        int bj  = m / T_;
        int t   = m - bj * T_;
        int n   = n_base + nn4;
        int h   = (n >> 5) & 7;
        int dd  = n & 31;
        size_t idx = (size_t)((bj * H_ + h) * T_ + t) * DH_ + dd;
        float4 val = *(const float4*)&Cs[mm * CSTR2 + nn4];
        __half2 p0 = __floats2half2_rn(val.x, val.y);
        __half2 p1 = __floats2half2_rn(val.z, val.w);
        uint2 u;
        u.x = *(uint32_t*)&p0;
        u.y = *(uint32_t*)&p1;
        *(uint2*)&dst[idx] = u;
    }
}

// ---------------------------------------------------------------------------
// Windowed attention v5 (R15-exact: 48.6us; single cp.async commit group).
// ---------------------------------------------------------------------------
#define KSTR 40   // halves
#define VSTR 40   // halves
#define OSTR 36   // floats
#define AOFF_V 34992
#define ATT_SMEM (AOFF_V + T_ * VSTR * 2)  // 54432 -> 4 CTAs/SM

__global__ void __launch_bounds__(256, 4)
attn_kernel(const float* __restrict__ tau, float* __restrict__ out)
{
    extern __shared__ char sma[];
    const uint32_t sb = smem_u32(sma);
    __half* Ks = (__half*)sma;
    __half* Vs = (__half*)(sma + AOFF_V);
    float*  Os = (float*)sma;

    const int bjh = blockIdx.x;
    const int bj  = bjh >> 3;
    const int h   = bjh & 7;
    const int b   = bj / J_;
    const int j   = bj - b * J_;
    const size_t base = (size_t)bjh * (T_ * DH_);

    const int t  = threadIdx.x;
    const bool tv = (t < T_);
    const int  tc = tv ? t : (T_ - 1);

    // Stage K, V via cp.async (16B granules, one commit group)
    {
        const char* kg = (const char*)(g_k + base);
        const char* vg = (const char*)(g_v + base);
        for (int i8 = threadIdx.x; i8 < T_ * DH_ / 8; i8 += 256) {
            int tt = i8 >> 2;
            int d8 = (i8 & 3) << 3;
            CP_ASYNC16(sb + (tt * KSTR + d8) * 2,          kg + i8 * 16);
            CP_ASYNC16(sb + AOFF_V + (tt * VSTR + d8) * 2, vg + i8 * 16);
        }
        CP_COMMIT();
    }

    // Q -> 16 half2 registers (overlaps staging)
    uint32_t qh[16];
    {
        const uint4* qrow = (const uint4*)(g_q + base + (size_t)tc * DH_);
        #pragma unroll
        for (int i = 0; i < 4; ++i) {
            uint4 u = qrow[i];
            qh[i * 4 + 0] = u.x; qh[i * 4 + 1] = u.y;
            qh[i * 4 + 2] = u.z; qh[i * 4 + 3] = u.w;
        }
    }

    const float scale = 1.0f / (sqrtf(32.0f) * fmaxf(tau[h], 1e-3f));

    int  tox[9];
    bool ov[9];
    #pragma unroll
    for (int o = 0; o < 9; ++o) {
        int to = tc + o - 4;
        ov[o]  = (to >= 0) && (to < T_);
        tox[o] = min(max(to, 0), T_ - 1);
    }

    CP_WAIT(0);
    __syncthreads();

    // ---- logits: LDS.128 fp16 K + packed hfma2 ----
    __half2 lac[9];
    #pragma unroll
    for (int o = 0; o < 9; ++o) lac[o] = __float2half2_rn(0.0f);

    #pragma unroll
    for (int d8 = 0; d8 < 4; ++d8) {
        const __half2 q0 = u2h2(qh[d8 * 4 + 0]);
        const __half2 q1 = u2h2(qh[d8 * 4 + 1]);
        const __half2 q2 = u2h2(qh[d8 * 4 + 2]);
        const __half2 q3 = u2h2(qh[d8 * 4 + 3]);
        #pragma unroll
        for (int o = 0; o < 9; ++o) {
            uint4 ku = *(const uint4*)&Ks[tox[o] * KSTR + d8 * 8];
            lac[o] = __hfma2(u2h2(ku.x), q0, lac[o]);
            lac[o] = __hfma2(u2h2(ku.y), q1, lac[o]);
            lac[o] = __hfma2(u2h2(ku.z), q2, lac[o]);
            lac[o] = __hfma2(u2h2(ku.w), q3, lac[o]);
        }
    }

    float logit[9];
    float mx = -1e30f;
    #pragma unroll
    for (int o = 0; o < 9; ++o) {
        float2 f = __half22float2(lac[o]);
        logit[o] = ov[o] ? (f.x + f.y) * scale : -1e30f;
        mx = fmaxf(mx, logit[o]);
    }
    float w[9];
    float s = 0.0f;
    #pragma unroll
    for (int o = 0; o < 9; ++o) {
        w[o] = ov[o] ? __expf(logit[o] - mx) : 0.0f;
        s += w[o];
    }
    const float inv = 1.0f / s;
    #pragma unroll
    for (int o = 0; o < 9; ++o) w[o] *= inv;

    __syncthreads();   // all K smem reads done before Os overlay

    // ---- V aggregation: uint4 LDS.128 + cvt + f32 FFMA ----
    #pragma unroll
    for (int d8 = 0; d8 < 4; ++d8) {
        float a[8];
        #pragma unroll
        for (int i = 0; i < 8; ++i) a[i] = 0.0f;
        #pragma unroll
        for (int o = 0; o < 9; ++o) {
            uint4 vu = *(const uint4*)&Vs[tox[o] * VSTR + d8 * 8];
            float2 v0 = h2f(vu.x), v1 = h2f(vu.y);
            float2 v2 = h2f(vu.z), v3 = h2f(vu.w);
            a[0] += w[o] * v0.x; a[1] += w[o] * v0.y;
            a[2] += w[o] * v1.x; a[3] += w[o] * v1.y;
            a[4] += w[o] * v2.x; a[5] += w[o] * v2.y;
            a[6] += w[o] * v3.x; a[7] += w[o] * v3.y;
        }
        if (tv) {
            *(float4*)&Os[tc * OSTR + d8 * 8]     = make_float4(a[0], a[1], a[2], a[3]);
            *(float4*)&Os[tc * OSTR + d8 * 8 + 4] = make_float4(a[4], a[5], a[6], a[7]);
        }
    }
    __syncthreads();

    // Coalesced output: out[b, t, j, h*32 + d]
    for (int i4 = threadIdx.x; i4 < T_ * DH_ / 4; i4 += 256) {
        int tt = i4 >> 3;
        int d4 = (i4 & 7) << 2;
        float4 a = *(const float4*)&Os[tt * OSTR + d4];
        float* orow = out + ((size_t)((b * T_ + tt) * J_ + j) * D_) + h * DH_;
        *(float4*)(orow + d4) = a;
    }
}

// ---------------------------------------------------------------------------
extern "C" void kernel_launch(void* const* d_in, const int* in_sizes, int n_in,
                              void* d_out, int out_size)
{
    (void)in_sizes; (void)n_in; (void)out_size;
    const float* x    = (const float*)d_in[0];
    const float* Wq   = (const float*)d_in[1];
    const float* bias = (const float*)d_in[2];
    const float* tau  = (const float*)d_in[3];
    float* out = (float*)d_out;

    cudaFuncSetAttribute(qkv_gemm,
                         cudaFuncAttributeMaxDynamicSharedMemorySize, GEMM_SMEM);
    cudaFuncSetAttribute(attn_kernel,
                         cudaFuncAttributeMaxDynamicSharedMemorySize, ATT_SMEM);

    convert_kernel<<<CONV_GRID, 256>>>(x, Wq);
    dim3 ggrid(N_ / BN, M_ / BM);   // (6, 729)
    qkv_gemm<<<ggrid, 256, GEMM_SMEM>>>(bias);
    attn_kernel<<<BJ_ * H_, 256, ATT_SMEM>>>(tau, out);
}